// round 7
// baseline (speedup 1.0000x reference)
#include <cuda_runtime.h>

// AccuracyMetricLoss: per-day (96-elem) RMS relative-error score, mean over days.
// score_d = (1 - sqrt(mean_j ((t-p)/max(t,thresh))^2)) * 100 ; out = mean_d score_d
//
// R7: software-pipelined (double-buffered) trips.
//  Evidence: occ 50/62/93% all give ~5.1TB/s -> not occupancy-limited. Theory:
//  each trip's compute tail (FFMA + 3x26cyc SHFL + sqrt) has ZERO loads
//  outstanding, capping Little's-law BW. Fix: prefetch trip i+1's 6 LDG.128
//  before computing trip i => loads outstanding ~continuously.
//  2 reg buffers (48 data regs) -> __launch_bounds__(256,3), 444 blocks
//  (3 CTAs/SM, one exact wave, 24 warps/SM; 24 x 3KB ~= 72KB in flight/SM).
// last-block-finalizes (deterministic fixed-order double sum, counter reset).

#define T_LEN 96
#define F4_PER_DAY 24
#define NBLOCKS 444          // 3 * 148 SMs
#define NTHREADS 256
#define WARPS_PER_BLOCK (NTHREADS / 32)
#define TOTAL_WARPS (NBLOCKS * WARPS_PER_BLOCK)

__device__ float g_partials[NBLOCKS];
__device__ unsigned int g_counter = 0;

__device__ __forceinline__ float day_err_sq(float4 t, float4 p, float thresh)
{
    float d0 = (t.x > thresh) ? t.x : thresh;
    float d1 = (t.y > thresh) ? t.y : thresh;
    float d2 = (t.z > thresh) ? t.z : thresh;
    float d3 = (t.w > thresh) ? t.w : thresh;
    float e0 = __fdividef(t.x - p.x, d0);
    float e1 = __fdividef(t.y - p.y, d1);
    float e2 = __fdividef(t.z - p.z, d2);
    float e3 = __fdividef(t.w - p.w, d3);
    return e0 * e0 + e1 * e1 + e2 * e2 + e3 * e3;
}

// load one 4-day trip (6 float4s) for this lane
#define LOAD_TRIP(T0,T1,T2,P0,P1,P2, dayv)                                  \
    do {                                                                    \
        const long _b = (long)((dayv) + g) * F4_PER_DAY + k;                \
        T0 = __ldcs(tru4  + _b);                                            \
        T1 = __ldcs(tru4  + _b + 8);                                        \
        T2 = __ldcs(tru4  + _b + 16);                                       \
        P0 = __ldcs(pred4 + _b);                                            \
        P1 = __ldcs(pred4 + _b + 8);                                        \
        P2 = __ldcs(pred4 + _b + 16);                                       \
    } while (0)

#define COMPUTE_TRIP(T0,T1,T2,P0,P1,P2)                                     \
    do {                                                                    \
        float _r = day_err_sq(T0, P0, thresh)                               \
                 + day_err_sq(T1, P1, thresh)                               \
                 + day_err_sq(T2, P2, thresh);                              \
        _r += __shfl_xor_sync(0xffffffffu, _r, 4);                          \
        _r += __shfl_xor_sync(0xffffffffu, _r, 2);                          \
        _r += __shfl_xor_sync(0xffffffffu, _r, 1);                          \
        acc += (1.0f - sqrtf(_r * inv_T)) * 100.0f;                         \
    } while (0)

__global__ __launch_bounds__(NTHREADS, 3) void score_kernel(
    const float* __restrict__ pred,
    const float* __restrict__ tru,
    float* __restrict__ out,
    int num_days)
{
    const float cap    = 1602.1333333333334f;
    const float thresh = 0.2f * cap;
    const float inv_T  = 1.0f / 96.0f;

    const int lane = threadIdx.x & 31;
    const int g    = lane >> 3;          // day group within warp (0..3)
    const int k    = lane & 7;           // lane within group
    const int warp = (blockIdx.x * WARPS_PER_BLOCK) + (threadIdx.x >> 5);

    const float4* __restrict__ tru4  = (const float4*)tru;
    const float4* __restrict__ pred4 = (const float4*)pred;

    // contiguous per-warp day range: near-perfect balance (<=1 day skew)
    int day_s = (int)(((long)warp       * num_days) / TOTAL_WARPS);
    int day_e = (int)(((long)(warp + 1) * num_days) / TOTAL_WARPS);

    float acc = 0.0f;

    int day = day_s;
    const int nfull = (day_e - day_s) >> 2;   // number of 4-day trips

    if (nfull > 0) {
        float4 ta0, ta1, ta2, pa0, pa1, pa2;  // buffer A
        float4 tb0, tb1, tb2, pb0, pb1, pb2;  // buffer B

        LOAD_TRIP(ta0, ta1, ta2, pa0, pa1, pa2, day);

        int i = 1;
        // steady state: always one trip's loads in flight while computing
        for (; i + 1 < nfull; i += 2) {
            LOAD_TRIP(tb0, tb1, tb2, pb0, pb1, pb2, day + 4);
            COMPUTE_TRIP(ta0, ta1, ta2, pa0, pa1, pa2);
            LOAD_TRIP(ta0, ta1, ta2, pa0, pa1, pa2, day + 8);
            COMPUTE_TRIP(tb0, tb1, tb2, pb0, pb1, pb2);
            day += 8;
        }
        if (i < nfull) {
            LOAD_TRIP(tb0, tb1, tb2, pb0, pb1, pb2, day + 4);
            COMPUTE_TRIP(ta0, ta1, ta2, pa0, pa1, pa2);
            COMPUTE_TRIP(tb0, tb1, tb2, pb0, pb1, pb2);
            day += 8;
        } else {
            COMPUTE_TRIP(ta0, ta1, ta2, pa0, pa1, pa2);
            day += 4;
        }
    }

    // tail: 0..3 days, groups g < nd active, same float4 path
    {
        const int nd = day_e - day;
        if (nd > 0) {
            float r = 0.0f;
            if (g < nd) {
                const long b = (long)(day + g) * F4_PER_DAY + k;
                float4 t0 = __ldcs(tru4  + b);
                float4 t1 = __ldcs(tru4  + b + 8);
                float4 t2 = __ldcs(tru4  + b + 16);
                float4 p0 = __ldcs(pred4 + b);
                float4 p1 = __ldcs(pred4 + b + 8);
                float4 p2 = __ldcs(pred4 + b + 16);
                r = day_err_sq(t0, p0, thresh)
                  + day_err_sq(t1, p1, thresh)
                  + day_err_sq(t2, p2, thresh);
            }
            r += __shfl_xor_sync(0xffffffffu, r, 4);
            r += __shfl_xor_sync(0xffffffffu, r, 2);
            r += __shfl_xor_sync(0xffffffffu, r, 1);
            if (g < nd)
                acc += (1.0f - sqrtf(r * inv_T)) * 100.0f;
        }
    }

    // warp sum, then block reduce into g_partials[blockIdx.x]
    #pragma unroll
    for (int o = 16; o > 0; o >>= 1)
        acc += __shfl_xor_sync(0xffffffffu, acc, o);

    __shared__ float warp_acc[WARPS_PER_BLOCK];
    if (lane == 0) warp_acc[threadIdx.x >> 5] = acc;
    __syncthreads();

    __shared__ bool is_last;
    if (threadIdx.x == 0) {
        float v = 0.0f;
        #pragma unroll
        for (int w = 0; w < WARPS_PER_BLOCK; w++) v += warp_acc[w];
        g_partials[blockIdx.x] = v;
        __threadfence();
        unsigned int prev = atomicAdd(&g_counter, 1u);
        is_last = (prev == (unsigned int)(gridDim.x - 1));
    }
    __syncthreads();

    // last block finalizes: fixed-order double reduction over NBLOCKS partials
    if (is_last) {
        double a = 0.0;
        for (int i = threadIdx.x; i < NBLOCKS; i += NTHREADS)
            a += (double)g_partials[i];

        __shared__ double dacc[WARPS_PER_BLOCK];
        #pragma unroll
        for (int o = 16; o > 0; o >>= 1)
            a += __shfl_xor_sync(0xffffffffu, a, o);
        if (lane == 0) dacc[threadIdx.x >> 5] = a;
        __syncthreads();
        if (threadIdx.x == 0) {
            double s = 0.0;
            #pragma unroll
            for (int w = 0; w < WARPS_PER_BLOCK; w++) s += dacc[w];
            out[0] = (float)(s / (8.0 * (double)num_days));
            g_counter = 0;           // reset for next graph replay
            __threadfence();
        }
    }
}

extern "C" void kernel_launch(void* const* d_in, const int* in_sizes, int n_in,
                              void* d_out, int out_size)
{
    const float* pred = (const float*)d_in[0];
    const float* tru  = (const float*)d_in[1];
    float* out = (float*)d_out;

    int num_days = in_sizes[0] / T_LEN;

    score_kernel<<<NBLOCKS, NTHREADS>>>(pred, tru, out, num_days);
}